// round 16
// baseline (speedup 1.0000x reference)
#include <cuda_runtime.h>
#include <cuda_bf16.h>
#include <math.h>
#include <stdint.h>

#define BB 2
#define LL 2048
#define DD 768
#define HH 12
#define RR 128
#define DH 64
#define NROWS (BB*LL)        // 4096
#define NC 32
#define CT 64
#define BHN (BB*HH)
#define PI_F 3.14159265358979323846f

typedef __nv_bfloat16 bf16;

// ---------------- scratch ---------------------------------------------------
__device__ float g_qkv[NROWS*3*DD];
__device__ float g_sem[NROWS*2*DD];
__device__ float g_ctx[NROWS*2*DD];
__device__ float g_kf[NROWS*DD];
__device__ float g_S[BHN*NC*DH*DH];
__device__ float g_z[BHN*NC*DH];

// bf16 split pairs
__device__ bf16 g_xn0[NROWS*DD], g_xn1[NROWS*DD];
__device__ bf16 g_x0[NROWS*DD],  g_x1[NROWS*DD];
__device__ bf16 g_hs0[NROWS*RR], g_hs1[NROWS*RR];
__device__ bf16 g_hc0[NROWS*RR], g_hc1[NROWS*RR];
__device__ bf16 g_at0[NROWS*DD], g_at1[NROWS*DD];
// weights, split + transposed to [N][K]
__device__ bf16 g_wq0[3*DD*DD],  g_wq1[3*DD*DD];
__device__ bf16 g_wsd0[RR*DD],   g_wsd1[RR*DD];
__device__ bf16 g_wcd0[RR*DD],   g_wcd1[RR*DD];
__device__ bf16 g_wsu0[2*DD*RR], g_wsu1[2*DD*RR];
__device__ bf16 g_wcu0[2*DD*RR], g_wcu1[2*DD*RR];
__device__ bf16 g_wp0[DD*DD],    g_wp1[DD*DD];

// ---------------- helpers ----------------------------------------------------
__device__ __forceinline__ uint32_t smem_u32p(const void* p) {
    uint32_t a;
    asm("{ .reg .u64 t; cvta.to.shared.u64 t, %1; cvt.u32.u64 %0, t; }" : "=r"(a) : "l"(p));
    return a;
}
__device__ __forceinline__ void mma_bf16(float* c, const uint32_t* a,
                                         uint32_t b0, uint32_t b1) {
    asm volatile(
        "mma.sync.aligned.m16n8k16.row.col.f32.bf16.bf16.f32 "
        "{%0,%1,%2,%3}, {%4,%5,%6,%7}, {%8,%9}, {%0,%1,%2,%3};"
        : "+f"(c[0]), "+f"(c[1]), "+f"(c[2]), "+f"(c[3])
        : "r"(a[0]), "r"(a[1]), "r"(a[2]), "r"(a[3]), "r"(b0), "r"(b1));
}
__device__ __forceinline__ void ldsm_x4(uint32_t* r, uint32_t addr) {
    asm volatile("ldmatrix.sync.aligned.m8n8.x4.shared.b16 {%0,%1,%2,%3}, [%4];"
        : "=r"(r[0]), "=r"(r[1]), "=r"(r[2]), "=r"(r[3]) : "r"(addr));
}
__device__ __forceinline__ void cp16(uint32_t sp, const void* gp) {
    asm volatile("cp.async.cg.shared.global [%0], [%1], 16;" :: "r"(sp), "l"(gp) : "memory");
}
__device__ __forceinline__ void split2(float v, bf16& h, bf16& l) {
    h = __float2bfloat16(v);
    l = __float2bfloat16(v - __bfloat162float(h));
}

// ---------------- split-bf16 GEMM (3-term, m16n8k16, ldmatrix, TN=64) --------
#define ST32 20
#define TN 64
#define NT (TN/16)
#define STAGE_U32 ((256 + 2*TN) * ST32)
#define SMEM64 (2 * STAGE_U32 * 4)               // 61440

template<int EPI>
__global__ void __launch_bounds__(256, 3) bgemm_kernel(
    const bf16* __restrict__ A0, const bf16* __restrict__ A1,
    const bf16* __restrict__ B0, const bf16* __restrict__ B1,
    const float* __restrict__ bias, float* __restrict__ Cf,
    bf16* __restrict__ C0, bf16* __restrict__ C1,
    int N, int K,
    const bf16* A0b, const bf16* A1b, const bf16* B0b, const bf16* B1b,
    float* Cfb, bf16* C0b, bf16* C1b) {
    if (blockIdx.z == 1) {
        if (A0b) { A0 = A0b; A1 = A1b; }
        B0 = B0b; B1 = B1b; Cf = Cfb; C0 = C0b; C1 = C1b;
    }
    extern __shared__ uint32_t smu[];
    uint32_t sbase = smem_u32p(smu);
    int tid = threadIdx.x;
    int lane = tid & 31, wid = tid >> 5;
    int wm = wid & 3, wn = wid >> 2;
    int g = lane >> 2, t4 = lane & 3;
    int m0 = blockIdx.y * 128, n0 = blockIdx.x * TN;

    int a_row = wm * 32 + (lane & 15);
    int a_col = (lane >> 4) << 2;
    int b_row = wn * (TN/2) + ((lane >> 4) << 3) + (lane & 7);
    int b_col = ((lane >> 3) & 1) << 2;

    float c[2][NT][4];
    #pragma unroll
    for (int mt = 0; mt < 2; mt++)
        #pragma unroll
        for (int nt = 0; nt < NT; nt++)
            #pragma unroll
            for (int r = 0; r < 4; r++) c[mt][nt][r] = 0.0f;

    int nstages = K >> 5;

    auto issue = [&](int s, int buf) {
        int k0 = s << 5;
        uint32_t so = sbase + buf * (STAGE_U32 * 4);
        #pragma unroll
        for (int i = 0; i < 2; i++) {
            int ch = tid + i * 256;
            int row = ch >> 2, q = ch & 3;
            uint32_t d = so + (row * ST32 + q * 4) * 4;
            cp16(d,                 A0 + (size_t)(m0 + row) * K + k0 + q * 8);
            cp16(d + 128*ST32*4,    A1 + (size_t)(m0 + row) * K + k0 + q * 8);
        }
        {
            int row = tid >> 2, q = tid & 3;
            uint32_t d = so + ((256 + row) * ST32 + q * 4) * 4;
            cp16(d,               B0 + (size_t)(n0 + row) * K + k0 + q * 8);
            cp16(d + TN*ST32*4,   B1 + (size_t)(n0 + row) * K + k0 + q * 8);
        }
        asm volatile("cp.async.commit_group;" ::: "memory");
    };

    issue(0, 0);
    for (int s = 0; s < nstages; s++) {
        int buf = s & 1;
        if (s + 1 < nstages) {
            issue(s + 1, buf ^ 1);
            asm volatile("cp.async.wait_group 1;" ::: "memory");
        } else {
            asm volatile("cp.async.wait_group 0;" ::: "memory");
        }
        __syncthreads();

        uint32_t stg = sbase + buf * (STAGE_U32 * 4);
        uint32_t pA0 = stg + (a_row * ST32 + a_col) * 4;
        uint32_t pA1 = pA0 + 128 * ST32 * 4;
        uint32_t pB0 = stg + ((256 + b_row) * ST32 + b_col) * 4;
        uint32_t pB1 = pB0 + TN * ST32 * 4;

        #pragma unroll
        for (int ks = 0; ks < 2; ks++) {
            int kb4 = ks * 32;
            uint32_t a0f[2][4], a1f[2][4];
            #pragma unroll
            for (int mt = 0; mt < 2; mt++) {
                ldsm_x4(a0f[mt], pA0 + mt * (16 * ST32 * 4) + kb4);
                ldsm_x4(a1f[mt], pA1 + mt * (16 * ST32 * 4) + kb4);
            }
            #pragma unroll
            for (int ntp = 0; ntp < NT/2; ntp++) {
                uint32_t b0r[4], b1r[4];
                ldsm_x4(b0r, pB0 + ntp * (16 * ST32 * 4) + kb4);
                ldsm_x4(b1r, pB1 + ntp * (16 * ST32 * 4) + kb4);
                #pragma unroll
                for (int mt = 0; mt < 2; mt++) {
                    mma_bf16(c[mt][2*ntp],   a0f[mt], b0r[0], b0r[1]);
                    mma_bf16(c[mt][2*ntp],   a0f[mt], b1r[0], b1r[1]);
                    mma_bf16(c[mt][2*ntp],   a1f[mt], b0r[0], b0r[1]);
                    mma_bf16(c[mt][2*ntp+1], a0f[mt], b0r[2], b0r[3]);
                    mma_bf16(c[mt][2*ntp+1], a0f[mt], b1r[2], b1r[3]);
                    mma_bf16(c[mt][2*ntp+1], a1f[mt], b0r[2], b0r[3]);
                }
            }
        }
        __syncthreads();
    }

    #pragma unroll
    for (int mt = 0; mt < 2; mt++) {
        int row = m0 + wm * 32 + mt * 16 + g;
        #pragma unroll
        for (int nt = 0; nt < NT; nt++) {
            int col = n0 + wn * (TN/2) + nt * 8 + 2 * t4;
            float v0 = c[mt][nt][0], v1 = c[mt][nt][1];
            float v2 = c[mt][nt][2], v3 = c[mt][nt][3];
            if (EPI == 1) {
                float b0 = bias[col], b1 = bias[col + 1];
                v0 += b0; v1 += b1; v2 += b0; v3 += b1;
            }
            if (EPI == 2) {
                v0 = v0 * __fdividef(1.0f, 1.0f + __expf(-v0));
                v1 = v1 * __fdividef(1.0f, 1.0f + __expf(-v1));
                v2 = v2 * __fdividef(1.0f, 1.0f + __expf(-v2));
                v3 = v3 * __fdividef(1.0f, 1.0f + __expf(-v3));
                bf16 h0, l0, h1, l1, h2, l2, h3, l3;
                split2(v0, h0, l0); split2(v1, h1, l1);
                split2(v2, h2, l2); split2(v3, h3, l3);
                __nv_bfloat162 ph0; ph0.x = h0; ph0.y = h1;
                __nv_bfloat162 pl0; pl0.x = l0; pl0.y = l1;
                __nv_bfloat162 ph1; ph1.x = h2; ph1.y = h3;
                __nv_bfloat162 pl1; pl1.x = l2; pl1.y = l3;
                *(__nv_bfloat162*)(C0 + (size_t)row * N + col)       = ph0;
                *(__nv_bfloat162*)(C1 + (size_t)row * N + col)       = pl0;
                *(__nv_bfloat162*)(C0 + (size_t)(row + 8) * N + col) = ph1;
                *(__nv_bfloat162*)(C1 + (size_t)(row + 8) * N + col) = pl1;
            } else {
                *(float2*)(Cf + (size_t)row * N + col)       = make_float2(v0, v1);
                *(float2*)(Cf + (size_t)(row + 8) * N + col) = make_float2(v2, v3);
            }
        }
    }
}

// ---------------- prep: weight split + layernorm (merged) --------------------
#define TQ  1728
#define TSD (TQ + 96)
#define TCD (TSD + 96)
#define TSU (TCD + 192)
#define TCU (TSU + 192)
#define TP  (TCU + 576)
__global__ void prep_kernel(
    const float* __restrict__ Wq, const float* __restrict__ Wsd,
    const float* __restrict__ Wcd, const float* __restrict__ Wsu,
    const float* __restrict__ Wcu, const float* __restrict__ Wp,
    const float* __restrict__ x, const float* __restrict__ gamma,
    const float* __restrict__ beta) {
    int bid = blockIdx.x;
    if (bid < TP) {
        int t = bid;
        const float* W; bf16 *D0, *D1; int K, N;
        if (t < TQ)       { W = Wq;  D0 = g_wq0;  D1 = g_wq1;  K = DD;  N = 3*DD; }
        else if (t < TSD) { t -= TQ;  W = Wsd; D0 = g_wsd0; D1 = g_wsd1; K = DD;  N = RR; }
        else if (t < TCD) { t -= TSD; W = Wcd; D0 = g_wcd0; D1 = g_wcd1; K = DD;  N = RR; }
        else if (t < TSU) { t -= TCD; W = Wsu; D0 = g_wsu0; D1 = g_wsu1; K = RR;  N = 2*DD; }
        else if (t < TCU) { t -= TSU; W = Wcu; D0 = g_wcu0; D1 = g_wcu1; K = RR;  N = 2*DD; }
        else              { t -= TCU; W = Wp;  D0 = g_wp0;  D1 = g_wp1;  K = DD;  N = DD; }
        int tN = N >> 5;
        int k0 = (t / tN) << 5, n0 = (t % tN) << 5;
        __shared__ float sm[32][33];
        int tx = threadIdx.x & 31, ty = threadIdx.x >> 5;
        #pragma unroll
        for (int i = 0; i < 4; i++)
            sm[ty + 8*i][tx] = W[(size_t)(k0 + ty + 8*i) * N + n0 + tx];
        __syncthreads();
        #pragma unroll
        for (int i = 0; i < 4; i++) {
            float v = sm[tx][ty + 8*i];
            bf16 h, l; split2(v, h, l);
            size_t o = (size_t)(n0 + ty + 8*i) * K + k0 + tx;
            D0[o] = h; D1[o] = l;
        }
    } else {
        int row = bid - TP;
        const float* xr = x + (size_t)row*DD;
        int t = threadIdx.x;
        float v0 = xr[t], v1 = xr[t+256], v2 = xr[t+512];
        __shared__ float red[256], red2[256];
        red[t]  = v0+v1+v2;
        red2[t] = v0*v0+v1*v1+v2*v2;
        __syncthreads();
        for (int o = 128; o > 0; o >>= 1) {
            if (t < o) { red[t] += red[t+o]; red2[t] += red2[t+o]; }
            __syncthreads();
        }
        float mu  = red[0] * (1.0f/DD);
        float var = red2[0] * (1.0f/DD) - mu*mu;
        float inv = rsqrtf(var + 1e-5f);
        size_t base = (size_t)row*DD;
        float vv[3] = {v0, v1, v2};
        #pragma unroll
        for (int i = 0; i < 3; i++) {
            int d = t + i*256;
            float xn = (vv[i]-mu)*inv*gamma[d] + beta[d];
            bf16 h, l;
            split2(xn, h, l);    g_xn0[base+d] = h; g_xn1[base+d] = l;
            split2(vv[i], h, l); g_x0[base+d]  = h; g_x1[base+d]  = l;
        }
    }
}

// ---------------- fused gate + chunk k(x)v sums -------------------------------
__device__ __forceinline__ float softplus_f(float a) {
    return a > 15.0f ? a : __logf(1.0f + __expf(a));
}
__device__ __forceinline__ float tanh_f(float a) {
    float x = fminf(fmaxf(a, -15.0f), 15.0f);
    float t = __expf(2.0f * x);
    return __fdividef(t - 1.0f, t + 1.0f);
}
__global__ void __launch_bounds__(256) gatechunk_kernel(
    const float* __restrict__ temperature, float* __restrict__ gate_out) {
    int c = blockIdx.x, bh = blockIdx.y;
    int b = bh / HH, h = bh - b*HH;
    __shared__ float  ksm[CT][DH+1];
    __shared__ float4 vsm[CT][DH/4];
    int tid = threadIdx.x;
    int i = tid >> 2, t4 = tid & 3;
    int gr = b*LL + c*CT + i;
    int d0 = h*DH + t4*16;
    float temp = temperature[0];
    const float* sr = g_sem + (size_t)gr*(2*DD);
    const float* cr = g_ctx + (size_t)gr*(2*DD);
    const float* qr = g_qkv + (size_t)gr*(3*DD);
    size_t hidb = ((size_t)bh*LL + c*CT + i)*DH + t4*16;
    #pragma unroll
    for (int r = 0; r < 4; r++) {
        float4 sa4 = *(const float4*)(sr + d0 + r*4);
        float4 sp4 = *(const float4*)(sr + DD + d0 + r*4);
        float4 ca4 = *(const float4*)(cr + d0 + r*4);
        float4 cp4 = *(const float4*)(cr + DD + d0 + r*4);
        float4 k4  = *(const float4*)(qr + DD + d0 + r*4);
        float4 v4  = *(const float4*)(qr + 2*DD + d0 + r*4);
        float sav[4] = {sa4.x, sa4.y, sa4.z, sa4.w};
        float spv[4] = {sp4.x, sp4.y, sp4.z, sp4.w};
        float cav[4] = {ca4.x, ca4.y, ca4.z, ca4.w};
        float cpv[4] = {cp4.x, cp4.y, cp4.z, cp4.w};
        float kv[4]  = {k4.x, k4.y, k4.z, k4.w};
        float gov[4], kfv[4];
        #pragma unroll
        for (int u = 0; u < 4; u++) {
            float sa = softplus_f(sav[u]);
            float sp = tanh_f(spv[u]) * PI_F;
            float ca = softplus_f(cav[u]);
            float cp = tanh_f(cpv[u]) * PI_F;
            float inter = sa * ca * __cosf(sp - cp) * temp;
            float gate = __fdividef(1.0f, 1.0f + __expf(-inter));
            gov[u] = gate;
            float k = kv[u] * (1.0f + gate);
            kfv[u] = k > 0.0f ? k + 1.0f : __expf(k);
            ksm[i][t4*16 + r*4 + u] = kfv[u];
        }
        vsm[i][t4*4 + r] = v4;
        *(float4*)(gate_out + (size_t)gr*DD + d0 + r*4) = make_float4(gov[0], gov[1], gov[2], gov[3]);
        *(float4*)(g_kf + hidb + r*4) = make_float4(kfv[0], kfv[1], kfv[2], kfv[3]);
    }
    __syncthreads();
    float4 acc[4] = {};
    float zacc = 0.0f;
    for (int l = 0; l < CT; l++) {
        float kd = ksm[l][i];
        zacc += kd;
        #pragma unroll
        for (int r = 0; r < 4; r++) {
            float4 v = vsm[l][t4*4 + r];
            acc[r].x += kd*v.x; acc[r].y += kd*v.y;
            acc[r].z += kd*v.z; acc[r].w += kd*v.w;
        }
    }
    float4* Sp = (float4*)(g_S + (size_t)(bh*NC + c)*DH*DH + i*DH + t4*16);
    #pragma unroll
    for (int r = 0; r < 4; r++) Sp[r] = acc[r];
    if (t4 == 0) g_z[(bh*NC + c)*DH + i] = zacc;
}

__global__ void scan_kernel() {
    int bh = blockIdx.x;
    int e = blockIdx.y * 256 + threadIdx.x;
    float* p = g_S + (size_t)bh*NC*DH*DH + e;
    float run = 0.0f;
    #pragma unroll
    for (int c = 0; c < NC; c++) {
        float t = p[(size_t)c*DH*DH];
        p[(size_t)c*DH*DH] = run;
        run += t;
    }
    if (blockIdx.y == 0 && threadIdx.x < DH) {
        float* pz = g_z + bh*NC*DH + threadIdx.x;
        float rz = 0.0f;
        #pragma unroll
        for (int c = 0; c < NC; c++) {
            float t = pz[c*DH];
            pz[c*DH] = rz;
            rz += t;
        }
    }
}

// attn: register-blocked scores + triangular S·V + inter-chunk contraction.
#define ATTN_SMEM ((CT*17 + CT*16 + CT*16)*16 + CT*68*4 + CT*4)
__global__ void __launch_bounds__(256) attn_kernel() {
    int c  = blockIdx.x;
    int bh = blockIdx.y;
    int b = bh / HH, h = bh - b*HH;
    extern __shared__ char asmem[];
    float4* qsm = (float4*)asmem;
    float4* ksm = qsm + CT*17;
    float4* vsm = ksm + CT*16;
    float*  ss  = (float*)(vsm + CT*16);
    float*  dens = ss + CT*68;
    int tid = threadIdx.x;

    for (int idx = tid; idx < CT*16; idx += 256) {
        int row = idx >> 4, kk = idx & 15;
        int gr = b*LL + c*CT + row;
        const float* qk = g_qkv + (size_t)gr*(3*DD) + h*DH;
        float4 q4 = *(const float4*)(qk + kk*4);
        q4.x = q4.x > 0.0f ? q4.x + 1.0f : __expf(q4.x);
        q4.y = q4.y > 0.0f ? q4.y + 1.0f : __expf(q4.y);
        q4.z = q4.z > 0.0f ? q4.z + 1.0f : __expf(q4.z);
        q4.w = q4.w > 0.0f ? q4.w + 1.0f : __expf(q4.w);
        qsm[row*17 + kk] = q4;
        vsm[row*16 + kk] = *(const float4*)(qk + 2*DD + kk*4);
        float4 k4 = *(const float4*)(g_kf + ((size_t)bh*LL + c*CT + row)*DH + kk*4);
        ksm[row*16 + (kk ^ ((row >> 2) & 15))] = k4;
    }
    __syncthreads();

    int ti = tid >> 4, tj = tid & 15;
    {
        float s[4][4] = {};
        #pragma unroll
        for (int kk = 0; kk < 16; kk++) {
            float4 qv[4], kv[4];
            #pragma unroll
            for (int ir = 0; ir < 4; ir++) qv[ir] = qsm[(4*ti + ir)*17 + kk];
            #pragma unroll
            for (int jc = 0; jc < 4; jc++) kv[jc] = ksm[(4*tj + jc)*16 + (kk ^ tj)];
            #pragma unroll
            for (int ir = 0; ir < 4; ir++)
                #pragma unroll
                for (int jc = 0; jc < 4; jc++)
                    s[ir][jc] += qv[ir].x*kv[jc].x + qv[ir].y*kv[jc].y
                               + qv[ir].z*kv[jc].z + qv[ir].w*kv[jc].w;
        }
        #pragma unroll
        for (int ir = 0; ir < 4; ir++)
            *(float4*)(ss + (4*ti + ir)*68 + 4*tj) =
                make_float4(s[ir][0], s[ir][1], s[ir][2], s[ir][3]);
    }
    __syncthreads();
    if (tid < CT) {
        const float* zp = g_z + (bh*NC + c)*DH;
        const float* qr = (const float*)qsm + tid*68;
        float den = 1e-6f;
        #pragma unroll 8
        for (int d = 0; d < DH; d++) den += qr[d] * zp[d];
        for (int j = 0; j <= tid; j++) den += ss[tid*68 + j];
        dens[tid] = den;
    }
    __syncthreads();
    const float* Sg = g_S + (size_t)(bh*NC + c)*DH*DH;
    const float* qb = (const float*)qsm;
    float4 acc[4] = {};
    #pragma unroll 8
    for (int kk = 0; kk < DH; kk++) {
        float4 Sv = *(const float4*)(Sg + kk*DH + tj*4);
        #pragma unroll
        for (int ir = 0; ir < 4; ir++) {
            float qd = qb[(4*ti + ir)*68 + kk];
            acc[ir].x += qd*Sv.x; acc[ir].y += qd*Sv.y;
            acc[ir].z += qd*Sv.z; acc[ir].w += qd*Sv.w;
        }
    }
    int jfull = 4*ti;
    for (int j = 0; j < jfull; j++) {
        float4 vv = vsm[j*16 + tj];
        #pragma unroll
        for (int ir = 0; ir < 4; ir++) {
            float sv = ss[(4*ti + ir)*68 + j];
            acc[ir].x += sv*vv.x; acc[ir].y += sv*vv.y;
            acc[ir].z += sv*vv.z; acc[ir].w += sv*vv.w;
        }
    }
    #pragma unroll
    for (int e = 0; e < 4; e++) {
        int j = jfull + e;
        float4 vv = vsm[j*16 + tj];
        #pragma unroll
        for (int ir = 0; ir < 4; ir++) {
            float sv = (ir >= e) ? ss[(4*ti + ir)*68 + j] : 0.0f;
            acc[ir].x += sv*vv.x; acc[ir].y += sv*vv.y;
            acc[ir].z += sv*vv.z; acc[ir].w += sv*vv.w;
        }
    }
    #pragma unroll
    for (int ir = 0; ir < 4; ir++) {
        int row = 4*ti + ir;
        float invd = __fdividef(1.0f, dens[row]);
        float o0 = acc[ir].x * invd, o1 = acc[ir].y * invd;
        float o2 = acc[ir].z * invd, o3 = acc[ir].w * invd;
        bf16 h0, l0, h1, l1, h2, l2, h3, l3;
        split2(o0, h0, l0); split2(o1, h1, l1);
        split2(o2, h2, l2); split2(o3, h3, l3);
        __nv_bfloat162 pa; pa.x = h0; pa.y = h1;
        __nv_bfloat162 pb; pb.x = h2; pb.y = h3;
        __nv_bfloat162 pc; pc.x = l0; pc.y = l1;
        __nv_bfloat162 pd; pd.x = l2; pd.y = l3;
        size_t obase = (size_t)(b*LL + c*CT + row)*DD + h*DH + tj*4;
        *(__nv_bfloat162*)(g_at0 + obase)     = pa;
        *(__nv_bfloat162*)(g_at0 + obase + 2) = pb;
        *(__nv_bfloat162*)(g_at1 + obase)     = pc;
        *(__nv_bfloat162*)(g_at1 + obase + 2) = pd;
    }
}

// ---------------- launch -------------------------------------------------------
extern "C" void kernel_launch(void* const* d_in, const int* in_sizes, int n_in,
                              void* d_out, int out_size) {
    const float* x          = (const float*)d_in[0];
    const float* W_qkv      = (const float*)d_in[1];
    const float* b_qkv      = (const float*)d_in[2];
    const float* W_sem_down = (const float*)d_in[3];
    const float* W_sem_up   = (const float*)d_in[4];
    const float* W_ctx_down = (const float*)d_in[5];
    const float* W_ctx_up   = (const float*)d_in[6];
    const float* temperature= (const float*)d_in[7];
    const float* W_proj     = (const float*)d_in[8];
    const float* b_proj     = (const float*)d_in[9];
    const float* gamma      = (const float*)d_in[10];
    const float* beta       = (const float*)d_in[11];
    float* y_out    = (float*)d_out;
    float* gate_out = y_out + (size_t)NROWS*DD;

    float *p_qkv, *p_sem, *p_ctx;
    bf16 *p_xn0, *p_xn1, *p_x0, *p_x1, *p_hs0, *p_hs1, *p_hc0, *p_hc1, *p_at0, *p_at1;
    bf16 *p_wq0, *p_wq1, *p_wsd0, *p_wsd1, *p_wcd0, *p_wcd1;
    bf16 *p_wsu0, *p_wsu1, *p_wcu0, *p_wcu1, *p_wp0, *p_wp1;
    cudaGetSymbolAddress((void**)&p_qkv, g_qkv);
    cudaGetSymbolAddress((void**)&p_sem, g_sem);
    cudaGetSymbolAddress((void**)&p_ctx, g_ctx);
    cudaGetSymbolAddress((void**)&p_xn0, g_xn0);  cudaGetSymbolAddress((void**)&p_xn1, g_xn1);
    cudaGetSymbolAddress((void**)&p_x0,  g_x0);   cudaGetSymbolAddress((void**)&p_x1,  g_x1);
    cudaGetSymbolAddress((void**)&p_hs0, g_hs0);  cudaGetSymbolAddress((void**)&p_hs1, g_hs1);
    cudaGetSymbolAddress((void**)&p_hc0, g_hc0);  cudaGetSymbolAddress((void**)&p_hc1, g_hc1);
    cudaGetSymbolAddress((void**)&p_at0, g_at0);  cudaGetSymbolAddress((void**)&p_at1, g_at1);
    cudaGetSymbolAddress((void**)&p_wq0, g_wq0);  cudaGetSymbolAddress((void**)&p_wq1, g_wq1);
    cudaGetSymbolAddress((void**)&p_wsd0,g_wsd0); cudaGetSymbolAddress((void**)&p_wsd1,g_wsd1);
    cudaGetSymbolAddress((void**)&p_wcd0,g_wcd0); cudaGetSymbolAddress((void**)&p_wcd1,g_wcd1);
    cudaGetSymbolAddress((void**)&p_wsu0,g_wsu0); cudaGetSymbolAddress((void**)&p_wsu1,g_wsu1);
    cudaGetSymbolAddress((void**)&p_wcu0,g_wcu0); cudaGetSymbolAddress((void**)&p_wcu1,g_wcu1);
    cudaGetSymbolAddress((void**)&p_wp0, g_wp0);  cudaGetSymbolAddress((void**)&p_wp1, g_wp1);

    static cudaStream_t s_side = nullptr;
    static cudaEvent_t evA = nullptr, evB = nullptr;
    static bool attr_set = false;
    if (!attr_set) {
        cudaFuncSetAttribute((const void*)bgemm_kernel<0>, cudaFuncAttributeMaxDynamicSharedMemorySize, SMEM64);
        cudaFuncSetAttribute((const void*)bgemm_kernel<1>, cudaFuncAttributeMaxDynamicSharedMemorySize, SMEM64);
        cudaFuncSetAttribute((const void*)bgemm_kernel<2>, cudaFuncAttributeMaxDynamicSharedMemorySize, SMEM64);
        cudaFuncSetAttribute((const void*)attn_kernel, cudaFuncAttributeMaxDynamicSharedMemorySize, ATTN_SMEM);
        cudaStreamCreateWithFlags(&s_side, cudaStreamNonBlocking);
        cudaEventCreateWithFlags(&evA, cudaEventDisableTiming);
        cudaEventCreateWithFlags(&evB, cudaEventDisableTiming);
        attr_set = true;
    }

    // prep: weight split + layernorm/input split (one launch)
    prep_kernel<<<TP + NROWS, 256>>>(W_qkv, W_sem_down, W_ctx_down, W_sem_up,
                                     W_ctx_up, W_proj, x, gamma, beta);
    cudaEventRecord(evA, 0);
    cudaStreamWaitEvent(s_side, evA, 0);

    // main stream: qkv GEMM  (4096 x 2304 x 768)
    bgemm_kernel<1><<<dim3(3*DD/TN, NROWS/128, 1), 256, SMEM64>>>(
        p_xn0, p_xn1, p_wq0, p_wq1, b_qkv, p_qkv, nullptr, nullptr, 3*DD, DD,
        nullptr, nullptr, nullptr, nullptr, nullptr, nullptr, nullptr);

    // side stream: down (silu, split out) then up
    bgemm_kernel<2><<<dim3(RR/TN, NROWS/128, 2), 256, SMEM64, s_side>>>(
        p_x0, p_x1, p_wsd0, p_wsd1, nullptr, nullptr, p_hs0, p_hs1, RR, DD,
        nullptr, nullptr, p_wcd0, p_wcd1, nullptr, p_hc0, p_hc1);
    bgemm_kernel<0><<<dim3(2*DD/TN, NROWS/128, 2), 256, SMEM64, s_side>>>(
        p_hs0, p_hs1, p_wsu0, p_wsu1, nullptr, p_sem, nullptr, nullptr, 2*DD, RR,
        p_hc0, p_hc1, p_wcu0, p_wcu1, p_ctx, nullptr, nullptr);
    cudaEventRecord(evB, s_side);
    cudaStreamWaitEvent(0, evB, 0);

    // fused gate + chunk sums
    gatechunk_kernel<<<dim3(NC, BHN), 256>>>(temperature, gate_out);
    scan_kernel<<<dim3(BHN, 16), 256>>>();
    attn_kernel<<<dim3(NC, BHN), 256, ATTN_SMEM>>>();

    // y = attn @ W_proj + b_proj        (4096 x 768 x 768)
    bgemm_kernel<1><<<dim3(DD/TN, NROWS/128, 1), 256, SMEM64>>>(
        p_at0, p_at1, p_wp0, p_wp1, b_proj, y_out, nullptr, nullptr, DD, DD,
        nullptr, nullptr, nullptr, nullptr, nullptr, nullptr, nullptr);
}